// round 7
// baseline (speedup 1.0000x reference)
#include <cuda_runtime.h>
#include <cuda_bf16.h>
#include <math.h>

// InnerCos: mean over rows of clamp(1 - cos_sim(x_i, centers[label_i]))
// x: [N, 256] f32, label: [N] i32, centers: [C, 256] f32 -> scalar f32

#define D_DIM 256
#define THREADS 256               // 8 warps
#define NW (THREADS / 32)
#define GROUP_ROWS 32             // rows consumed per CTA iteration
#define CTAS_PER_SM 3

// Pre-normalized centers (c / ||c||), C <= 256
__device__ float g_cnorm[256 * D_DIM];

// ---- Prologue: one warp per center, normalize into g_cnorm; also zero out ----
__global__ void center_norm_kernel(const float* __restrict__ cen, int C,
                                   float* __restrict__ out)
{
    const int c    = blockIdx.x;
    const int lane = threadIdx.x;
    if (c == 0 && lane == 0) *out = 0.0f;
    const float4* row = reinterpret_cast<const float4*>(cen + (size_t)c * D_DIM);
    float4 v0 = __ldg(row + lane);
    float4 v1 = __ldg(row + lane + 32);
    float s = v0.x*v0.x + v0.y*v0.y + v0.z*v0.z + v0.w*v0.w
            + v1.x*v1.x + v1.y*v1.y + v1.z*v1.z + v1.w*v1.w;
    #pragma unroll
    for (int o = 16; o > 0; o >>= 1)
        s += __shfl_xor_sync(0xffffffffu, s, o);
    float inv = rsqrtf(fmaxf(s, 1e-30f));
    v0.x *= inv; v0.y *= inv; v0.z *= inv; v0.w *= inv;
    v1.x *= inv; v1.y *= inv; v1.z *= inv; v1.w *= inv;
    float4* dst = reinterpret_cast<float4*>(g_cnorm + (size_t)c * D_DIM);
    dst[lane] = v0;
    dst[lane + 32] = v1;
}

// ---- Main: single balanced wave; 8 lanes/row; register double-buffer ----
__global__ void __launch_bounds__(THREADS, CTAS_PER_SM)
inner_cos_kernel(const float* __restrict__ x,
                 const int* __restrict__ lab,
                 float* __restrict__ out,
                 int N, int groups_total, int per_cta, float invN)
{
    const int tid  = threadIdx.x;
    const int lane = tid & 31;
    const int warp = tid >> 5;
    const int sub  = lane >> 3;   // warp's row 0..3 within a group
    const int sl   = lane & 7;    // owns 8 float4 of the row

    const int g0   = blockIdx.x * per_cta;
    const int g1   = min(g0 + per_cta, groups_total);
    const int nits = g1 - g0;

    // row offset of this lane within any group
    const int roff = warp * 4 + sub;

    float acc = 0.0f;

    if (nits > 0) {
        // ---- pipeline prologue: group g0 loads ----
        int r0 = g0 * GROUP_ROWS + roff;
        int lb = (r0 < N) ? __ldg(lab + r0) : 0;
        float4 a[8];
        {
            const float4* xr = reinterpret_cast<const float4*>(
                x + (size_t)min(r0, N - 1) * D_DIM);
            #pragma unroll
            for (int j = 0; j < 8; ++j)
                a[j] = __ldg(xr + sl + 8 * j);
        }

        #pragma unroll 2
        for (int it = 0; it < nits; ++it) {
            const bool v      = (g0 + it) * GROUP_ROWS + roff < N;
            const int  lb_cur = lb;

            // ---- issue NEXT group's loads first (keep DRAM queue full) ----
            float4 b[8];
            if (it + 1 < nits) {
                const int rn = (g0 + it + 1) * GROUP_ROWS + roff;
                lb = (rn < N) ? __ldg(lab + rn) : 0;
                const float4* xn = reinterpret_cast<const float4*>(
                    x + (size_t)min(rn, N - 1) * D_DIM);
                #pragma unroll
                for (int j = 0; j < 8; ++j)
                    b[j] = __ldg(xn + sl + 8 * j);
            }

            // ---- compute on CURRENT group ----
            const float4* cr = reinterpret_cast<const float4*>(
                g_cnorm + (size_t)lb_cur * D_DIM);

            float dot0 = 0.f, dot1 = 0.f, nx0 = 0.f, nx1 = 0.f;
            #pragma unroll
            for (int j = 0; j < 8; j += 2) {
                float4 c0 = cr[sl + 8 * j];        // L1-resident
                float4 c1 = cr[sl + 8 * (j + 1)];
                dot0 = fmaf(a[j].x, c0.x, fmaf(a[j].y, c0.y,
                       fmaf(a[j].z, c0.z, fmaf(a[j].w, c0.w, dot0))));
                nx0  = fmaf(a[j].x, a[j].x, fmaf(a[j].y, a[j].y,
                       fmaf(a[j].z, a[j].z, fmaf(a[j].w, a[j].w, nx0))));
                dot1 = fmaf(a[j+1].x, c1.x, fmaf(a[j+1].y, c1.y,
                       fmaf(a[j+1].z, c1.z, fmaf(a[j+1].w, c1.w, dot1))));
                nx1  = fmaf(a[j+1].x, a[j+1].x, fmaf(a[j+1].y, a[j+1].y,
                       fmaf(a[j+1].z, a[j+1].z, fmaf(a[j+1].w, a[j+1].w, nx1))));
            }
            float dot = dot0 + dot1;
            float nx2 = nx0 + nx1;

            #pragma unroll
            for (int o = 4; o > 0; o >>= 1) {      // reduce across 8-lane group
                dot += __shfl_xor_sync(0xffffffffu, dot, o);
                nx2 += __shfl_xor_sync(0xffffffffu, nx2, o);
            }

            if (sl == 0 && v) {
                float cos = dot * rsqrtf(fmaxf(nx2, 1e-30f));
                acc += fminf(fmaxf(1.0f - cos, 1e-12f), 1e12f);
            }

            // ---- rotate pipeline ----
            if (it + 1 < nits) {
                #pragma unroll
                for (int j = 0; j < 8; ++j) a[j] = b[j];
            }
        }
    }

    // ---- warp reduce (acc nonzero only on sl==0 lanes), block, one atomic ----
    #pragma unroll
    for (int o = 16; o > 0; o >>= 1)
        acc += __shfl_xor_sync(0xffffffffu, acc, o);

    __shared__ float wsum[NW];
    if (lane == 0) wsum[warp] = acc;
    __syncthreads();
    if (tid == 0) {
        float s = 0.0f;
        #pragma unroll
        for (int i = 0; i < NW; ++i) s += wsum[i];
        atomicAdd(out, s * invN);
    }
}

extern "C" void kernel_launch(void* const* d_in, const int* in_sizes, int n_in,
                              void* d_out, int out_size)
{
    const float* x   = (const float*)d_in[0];   // ref_emb [N, 256]
    const int*   lab = (const int*)d_in[1];     // ref_label [N]
    const float* cen = (const float*)d_in[2];   // centers [C, 256]
    float* out = (float*)d_out;

    const int N = in_sizes[1];
    const int C = in_sizes[2] / D_DIM;

    static int sm_count = 0;
    if (sm_count == 0)
        cudaDeviceGetAttribute(&sm_count, cudaDevAttrMultiProcessorCount, 0);

    const int grid = sm_count * CTAS_PER_SM;           // exactly one wave
    const int groups_total = (N + GROUP_ROWS - 1) / GROUP_ROWS;
    const int per_cta = (groups_total + grid - 1) / grid;

    center_norm_kernel<<<C, 32>>>(cen, C, out);

    inner_cos_kernel<<<grid, THREADS>>>(x, lab, out, N,
                                        groups_total, per_cta,
                                        1.0f / (float)N);
}

// round 8
// speedup vs baseline: 1.2626x; 1.2626x over previous
#include <cuda_runtime.h>
#include <cuda_bf16.h>
#include <math.h>

// InnerCos: mean over rows of clamp(1 - cos_sim(x_i, centers[label_i]))
// x: [N, 256] f32, label: [N] i32, centers: [C, 64] f32 -> scalar f32

#define D_DIM 256
#define THREADS 256               // 8 warps
#define NW (THREADS / 32)
#define GROUPS 2                  // compile-time static; 32 rows per group
#define ROWS_PER_BLOCK (GROUPS * 32)   // 64 -> grid 4096, T_CTA ~5us (small tail)

// Pre-normalized centers (c / ||c||), C <= 256
__device__ float g_cnorm[256 * D_DIM];

// ---- Prologue: one warp per center, normalize into g_cnorm; also zero out ----
__global__ void center_norm_kernel(const float* __restrict__ cen, int C,
                                   float* __restrict__ out)
{
    const int c    = blockIdx.x;
    const int lane = threadIdx.x;
    if (c == 0 && lane == 0) *out = 0.0f;
    const float4* row = reinterpret_cast<const float4*>(cen + (size_t)c * D_DIM);
    float4 v0 = __ldg(row + lane);
    float4 v1 = __ldg(row + lane + 32);
    float s = v0.x*v0.x + v0.y*v0.y + v0.z*v0.z + v0.w*v0.w
            + v1.x*v1.x + v1.y*v1.y + v1.z*v1.z + v1.w*v1.w;
    #pragma unroll
    for (int o = 16; o > 0; o >>= 1)
        s += __shfl_xor_sync(0xffffffffu, s, o);
    float inv = rsqrtf(fmaxf(s, 1e-30f));
    v0.x *= inv; v0.y *= inv; v0.z *= inv; v0.w *= inv;
    v1.x *= inv; v1.y *= inv; v1.z *= inv; v1.w *= inv;
    float4* dst = reinterpret_cast<float4*>(g_cnorm + (size_t)c * D_DIM);
    dst[lane] = v0;
    dst[lane + 32] = v1;
}

// ---- Main: 8 lanes/row, 4 rows/warp, register double-buffer, static unroll ----
__global__ void __launch_bounds__(THREADS, 3)
inner_cos_kernel(const float* __restrict__ x,
                 const int* __restrict__ lab,
                 float* __restrict__ out,
                 int N, float invN)
{
    const int tid  = threadIdx.x;
    const int lane = tid & 31;
    const int warp = tid >> 5;
    const int sub  = lane >> 3;   // warp's row 0..3 within a group
    const int sl   = lane & 7;    // owns 8 float4 of the row

    // row for iteration it: rbase + it * 32
    const int rbase = blockIdx.x * ROWS_PER_BLOCK + warp * 4 + sub;

    float acc = 0.0f;

    // ---- pipeline prologue: group 0 loads ----
    int   r0  = rbase;
    int   lb  = (r0 < N) ? __ldg(lab + r0) : 0;
    float4 a[8];
    {
        const float4* xr = reinterpret_cast<const float4*>(
            x + (size_t)min(r0, N - 1) * D_DIM);
        #pragma unroll
        for (int j = 0; j < 8; ++j)
            a[j] = __ldg(xr + sl + 8 * j);
    }

    #pragma unroll
    for (int it = 0; it < GROUPS; ++it) {
        const bool v      = (rbase + it * 32) < N;
        const int  lb_cur = lb;

        // ---- issue NEXT group's loads first (keep DRAM queue full) ----
        float4 b[8];
        if (it + 1 < GROUPS) {
            const int rn = rbase + (it + 1) * 32;
            lb = (rn < N) ? __ldg(lab + rn) : 0;
            const float4* xn = reinterpret_cast<const float4*>(
                x + (size_t)min(rn, N - 1) * D_DIM);
            #pragma unroll
            for (int j = 0; j < 8; ++j)
                b[j] = __ldg(xn + sl + 8 * j);
        }

        // ---- compute on CURRENT group ----
        const float4* cr = reinterpret_cast<const float4*>(
            g_cnorm + (size_t)lb_cur * D_DIM);

        float dot0 = 0.f, dot1 = 0.f, nx0 = 0.f, nx1 = 0.f;
        #pragma unroll
        for (int j = 0; j < 8; j += 2) {
            float4 c0 = cr[sl + 8 * j];        // L1-resident
            float4 c1 = cr[sl + 8 * (j + 1)];
            dot0 = fmaf(a[j].x, c0.x, fmaf(a[j].y, c0.y,
                   fmaf(a[j].z, c0.z, fmaf(a[j].w, c0.w, dot0))));
            nx0  = fmaf(a[j].x, a[j].x, fmaf(a[j].y, a[j].y,
                   fmaf(a[j].z, a[j].z, fmaf(a[j].w, a[j].w, nx0))));
            dot1 = fmaf(a[j+1].x, c1.x, fmaf(a[j+1].y, c1.y,
                   fmaf(a[j+1].z, c1.z, fmaf(a[j+1].w, c1.w, dot1))));
            nx1  = fmaf(a[j+1].x, a[j+1].x, fmaf(a[j+1].y, a[j+1].y,
                   fmaf(a[j+1].z, a[j+1].z, fmaf(a[j+1].w, a[j+1].w, nx1))));
        }
        float dot = dot0 + dot1;
        float nx2 = nx0 + nx1;

        #pragma unroll
        for (int o = 4; o > 0; o >>= 1) {      // reduce across the 8-lane group
            dot += __shfl_xor_sync(0xffffffffu, dot, o);
            nx2 += __shfl_xor_sync(0xffffffffu, nx2, o);
        }

        if (sl == 0 && v) {
            float cos = dot * rsqrtf(fmaxf(nx2, 1e-30f));
            acc += fminf(fmaxf(1.0f - cos, 1e-12f), 1e12f);
        }

        // ---- rotate pipeline ----
        if (it + 1 < GROUPS) {
            #pragma unroll
            for (int j = 0; j < 8; ++j) a[j] = b[j];
        }
    }

    // ---- warp reduce (acc nonzero only on sl==0 lanes), block, one atomic ----
    #pragma unroll
    for (int o = 16; o > 0; o >>= 1)
        acc += __shfl_xor_sync(0xffffffffu, acc, o);

    __shared__ float wsum[NW];
    if (lane == 0) wsum[warp] = acc;
    __syncthreads();
    if (tid == 0) {
        float s = 0.0f;
        #pragma unroll
        for (int i = 0; i < NW; ++i) s += wsum[i];
        atomicAdd(out, s * invN);
    }
}

extern "C" void kernel_launch(void* const* d_in, const int* in_sizes, int n_in,
                              void* d_out, int out_size)
{
    const float* x   = (const float*)d_in[0];   // ref_emb [N, 256]
    const int*   lab = (const int*)d_in[1];     // ref_label [N]
    const float* cen = (const float*)d_in[2];   // centers [C, 256]
    float* out = (float*)d_out;

    const int N = in_sizes[1];
    const int C = in_sizes[2] / D_DIM;

    center_norm_kernel<<<C, 32>>>(cen, C, out);

    const int blocks = (N + ROWS_PER_BLOCK - 1) / ROWS_PER_BLOCK;
    inner_cos_kernel<<<blocks, THREADS>>>(x, lab, out, N, 1.0f / (float)N);
}